// round 1
// baseline (speedup 1.0000x reference)
#include <cuda_runtime.h>
#include <math.h>

#define BB 32
#define LL 1024
#define BLT (BB*LL)
#define DIN 63
#define DM 256
#define NCLS 14
#define NLAYER 4
#define DI 512
#define DS 128
#define NHH 8
#define HPP 64
#define DCV 4
#define CCH 768
#define PRJ 1288
#define EPSF 1e-5f

// ---------------- scratch (device globals; no cudaMalloc allowed) ----------
__device__ float g_h[BLT*DM];                 // 33.5 MB residual/stream
__device__ float g_zx[(size_t)BLT*PRJ];       // 168 MB inproj output
__device__ float g_xbc[(size_t)BLT*CCH];      // 100 MB conv+silu output
__device__ float g_dt[BLT*NHH];
__device__ float g_dA[BLT*NHH];
__device__ float g_y[(size_t)BLT*DI];         // 67 MB scan output / rms / gemm A
__device__ float g_m[BLT*DM];                 // 33.5 MB outproj output
__device__ float g_pool[BB*DM];

// ---------------- block layernorm helper (blockDim == 256) -----------------
__device__ __forceinline__ void ln_write256(float acc, float* outp,
                                            const float* __restrict__ w,
                                            const float* __restrict__ b, int j) {
    __shared__ float s1[8], s2[8];
    float v = acc, v2 = acc * acc;
    int lane = j & 31, wp = j >> 5;
#pragma unroll
    for (int o = 16; o > 0; o >>= 1) {
        v  += __shfl_down_sync(0xffffffffu, v,  o);
        v2 += __shfl_down_sync(0xffffffffu, v2, o);
    }
    if (lane == 0) { s1[wp] = v; s2[wp] = v2; }
    __syncthreads();
    if (j == 0) {
        float a = 0.f, c = 0.f;
#pragma unroll
        for (int i = 0; i < 8; i++) { a += s1[i]; c += s2[i]; }
        s1[0] = a * (1.f / DM);
        s2[0] = c * (1.f / DM);
    }
    __syncthreads();
    float mu = s1[0], var = s2[0] - mu * mu;
    outp[j] = (acc - mu) * rsqrtf(var + EPSF) * w[j] + b[j];
}

// ---------------- input projection + layernorm ------------------------------
__global__ __launch_bounds__(256) void k_in_ln(const float* __restrict__ x,
                                               const float* __restrict__ w,
                                               const float* __restrict__ bias,
                                               const float* __restrict__ gw,
                                               const float* __restrict__ gb) {
    int row = blockIdx.x, j = threadIdx.x;
    __shared__ float sx[DIN];
    if (j < DIN) sx[j] = x[(size_t)row * DIN + j];
    __syncthreads();
    const float* wr = w + j * DIN;
    float acc = bias[j];
#pragma unroll
    for (int k = 0; k < DIN; k++) acc += sx[k] * wr[k];
    ln_write256(acc, g_h + (size_t)row * DM, gw, gb, j);
}

// ---------------- fp32 tiled GEMM: C[M,N] = A[M,K] @ B[N,K]^T ---------------
// BM=BN=128, BK=16, 256 threads, 8x8 per thread (quadrant split).
#define GBM 128
#define GBN 128
#define GBK 16
#define GPAD 132
__global__ __launch_bounds__(256) void gemm_nt(const float* __restrict__ A,
                                               const float* __restrict__ B,
                                               float* __restrict__ C,
                                               int M, int N, int K) {
    __shared__ __align__(16) float As[GBK][GPAD];
    __shared__ __align__(16) float Bs[GBK][GPAD];
    int bm = blockIdx.y * GBM, bn = blockIdx.x * GBN;
    int tid = threadIdx.x;
    int tr = tid >> 4, tc = tid & 15;
    float acc[8][8];
#pragma unroll
    for (int i = 0; i < 8; i++)
#pragma unroll
        for (int j = 0; j < 8; j++) acc[i][j] = 0.f;

    for (int k0 = 0; k0 < K; k0 += GBK) {
#pragma unroll
        for (int i = 0; i < 2; i++) {
            int idx = tid + i * 256;           // 0..511
            int r = idx >> 2, c4 = (idx & 3) * 4;
            float4 v = *(const float4*)(A + (size_t)(bm + r) * K + k0 + c4);
            As[c4 + 0][r] = v.x; As[c4 + 1][r] = v.y;
            As[c4 + 2][r] = v.z; As[c4 + 3][r] = v.w;
        }
#pragma unroll
        for (int i = 0; i < 2; i++) {
            int idx = tid + i * 256;
            int r = idx >> 2, c4 = (idx & 3) * 4;
            float4 v = make_float4(0.f, 0.f, 0.f, 0.f);
            if (bn + r < N) v = *(const float4*)(B + (size_t)(bn + r) * K + k0 + c4);
            Bs[c4 + 0][r] = v.x; Bs[c4 + 1][r] = v.y;
            Bs[c4 + 2][r] = v.z; Bs[c4 + 3][r] = v.w;
        }
        __syncthreads();
#pragma unroll
        for (int k = 0; k < GBK; k++) {
            float av[8], bv[8];
            *(float4*)&av[0] = *(const float4*)&As[k][tr * 4];
            *(float4*)&av[4] = *(const float4*)&As[k][64 + tr * 4];
            *(float4*)&bv[0] = *(const float4*)&Bs[k][tc * 4];
            *(float4*)&bv[4] = *(const float4*)&Bs[k][64 + tc * 4];
#pragma unroll
            for (int i = 0; i < 8; i++)
#pragma unroll
                for (int j = 0; j < 8; j++) acc[i][j] += av[i] * bv[j];
        }
        __syncthreads();
    }
    // store (N multiple of 4; col-validity uniform within each float4)
    int c0 = bn + tc * 4, c1 = bn + 64 + tc * 4;
#pragma unroll
    for (int half = 0; half < 2; half++) {
#pragma unroll
        for (int i = 0; i < 4; i++) {
            int r = bm + half * 64 + tr * 4 + i;
            float* crow = C + (size_t)r * N;
            int ai = half * 4 + i;
            if (c0 < N) {
                float4 v = make_float4(acc[ai][0], acc[ai][1], acc[ai][2], acc[ai][3]);
                *(float4*)(crow + c0) = v;
            }
            if (c1 < N) {
                float4 v = make_float4(acc[ai][4], acc[ai][5], acc[ai][6], acc[ai][7]);
                *(float4*)(crow + c1) = v;
            }
        }
    }
}

// ---------------- causal depthwise conv + silu ------------------------------
__global__ __launch_bounds__(256) void k_conv(const float* __restrict__ cw,
                                              const float* __restrict__ cb) {
    int idx = blockIdx.x * 256 + threadIdx.x;      // BLT*CCH exact multiple
    int c = idx % CCH;
    int row = idx / CCH;
    int t = row & (LL - 1);
    const float* base = g_zx + (size_t)row * PRJ + DI + c;
    float acc = cb[c];
#pragma unroll
    for (int k = 0; k < DCV; k++) {
        int tt = t + k - (DCV - 1);
        if (tt >= 0) acc += base[(long)(k - (DCV - 1)) * PRJ] * cw[k * CCH + c];
    }
    float s = acc / (1.f + expf(-acc));
    g_xbc[(size_t)row * CCH + c] = s;
}

// ---------------- dt = softplus(dt + bias), dA = exp(dt * -exp(A_log)) -----
__global__ __launch_bounds__(256) void k_dt(const float* __restrict__ dtb,
                                            const float* __restrict__ alog) {
    int idx = blockIdx.x * 256 + threadIdx.x;      // BLT*NHH exact multiple
    int row = idx >> 3, hh = idx & 7;
    float v = g_zx[(size_t)row * PRJ + DI + CCH + hh] + dtb[hh];
    float dt = (v > 20.f) ? v : log1pf(expf(v));
    float A = -expf(alog[hh]);
    g_dt[idx] = dt;
    g_dA[idx] = expf(dt * A);
}

// ---------------- sequential SSM scan ---------------------------------------
// one block per (b,h); 256 threads; thread tile 4(p) x 8(n); state in regs.
__global__ __launch_bounds__(256) void k_scan(const float* __restrict__ Dp) {
    int bh = blockIdx.x, b = bh >> 3, hh = bh & 7;
    int tid = threadIdx.x;
    int pg = tid >> 4, ng = tid & 15;
    int p0 = pg * 4, n0 = ng * 8;
    float hs[4][8];
#pragma unroll
    for (int i = 0; i < 4; i++)
#pragma unroll
        for (int j = 0; j < 8; j++) hs[i][j] = 0.f;

    __shared__ __align__(16) float sB[DS], sC[DS], sX[HPP];
    __shared__ float sSc[2];
    float Dh = Dp[hh];
    const float* xrow = g_xbc + (size_t)b * LL * CCH;
    const float* zrow = g_zx + (size_t)b * LL * PRJ + hh * HPP;
    float* yrow = g_y + (size_t)b * LL * DI + hh * HPP;
    const float* dAp = g_dA + (size_t)(b * LL) * NHH + hh;
    const float* dtp = g_dt + (size_t)(b * LL) * NHH + hh;

    for (int t = 0; t < LL; t++) {
        const float* xr = xrow + (size_t)t * CCH;
        if (tid < 128) sB[tid] = xr[DI + tid];
        else           sC[tid - 128] = xr[DI + DS + tid - 128];
        if (tid < 64)  sX[tid] = xr[hh * HPP + tid];
        else if (tid == 64) { sSc[0] = dAp[t * NHH]; sSc[1] = dtp[t * NHH]; }
        __syncthreads();

        float dA = sSc[0], dtv = sSc[1];
        float xv[4], dtx[4], acc[4];
#pragma unroll
        for (int i = 0; i < 4; i++) {
            xv[i] = sX[p0 + i];
            dtx[i] = dtv * xv[i];
            acc[i] = 0.f;
        }
        float bq[8], cq[8];
        *(float4*)&bq[0] = *(const float4*)&sB[n0];
        *(float4*)&bq[4] = *(const float4*)&sB[n0 + 4];
        *(float4*)&cq[0] = *(const float4*)&sC[n0];
        *(float4*)&cq[4] = *(const float4*)&sC[n0 + 4];
#pragma unroll
        for (int i = 0; i < 4; i++)
#pragma unroll
            for (int j = 0; j < 8; j++) {
                hs[i][j] = hs[i][j] * dA + dtx[i] * bq[j];
                acc[i] += hs[i][j] * cq[j];
            }
#pragma unroll
        for (int o = 8; o > 0; o >>= 1)
#pragma unroll
            for (int i = 0; i < 4; i++)
                acc[i] += __shfl_down_sync(0xffffffffu, acc[i], o, 16);
        if (ng == 0) {
#pragma unroll
            for (int i = 0; i < 4; i++) {
                float z = zrow[(size_t)t * PRJ + p0 + i];
                float sz = z / (1.f + expf(-z));
                yrow[(size_t)t * DI + p0 + i] = (acc[i] + Dh * xv[i]) * sz;
            }
        }
        __syncthreads();
    }
}

// ---------------- RMS norm over 512 (in place on g_y) -----------------------
__global__ __launch_bounds__(256) void k_rms(const float* __restrict__ nw) {
    int row = blockIdx.x, j = threadIdx.x;
    float a0 = g_y[(size_t)row * DI + j];
    float a1 = g_y[(size_t)row * DI + 256 + j];
    float v = a0 * a0 + a1 * a1;
    __shared__ float s1[8];
    int lane = j & 31, w = j >> 5;
#pragma unroll
    for (int o = 16; o > 0; o >>= 1) v += __shfl_down_sync(0xffffffffu, v, o);
    if (lane == 0) s1[w] = v;
    __syncthreads();
    if (j == 0) {
        float a = 0.f;
#pragma unroll
        for (int i = 0; i < 8; i++) a += s1[i];
        s1[0] = a * (1.f / DI);
    }
    __syncthreads();
    float sc = rsqrtf(s1[0] + EPSF);
    g_y[(size_t)row * DI + j]       = a0 * sc * nw[j];
    g_y[(size_t)row * DI + 256 + j] = a1 * sc * nw[j + 256];
}

// ---------------- residual add + layernorm (writes g_h) ---------------------
__global__ __launch_bounds__(256) void k_addln(const float* __restrict__ lw,
                                               const float* __restrict__ lb) {
    int row = blockIdx.x, j = threadIdx.x;
    size_t idx = (size_t)row * DM + j;
    float acc = g_m[idx] + g_h[idx];
    ln_write256(acc, g_h + (size_t)row * DM, lw, lb, j);
}

// ---------------- masked mean pool -------------------------------------------
__global__ __launch_bounds__(256) void k_pool(const int* __restrict__ lengths) {
    int b = blockIdx.x, d = threadIdx.x;
    int len = lengths[b];
    float acc = 0.f;
    const float* base = g_h + (size_t)b * LL * DM + d;
    for (int t = 0; t < len; t++) acc += base[(size_t)t * DM];
    g_pool[b * DM + d] = acc / (float)len;
}

// ---------------- classification head ---------------------------------------
__global__ __launch_bounds__(NCLS*32) void k_head(const float* __restrict__ hw,
                                                  const float* __restrict__ hb,
                                                  float* __restrict__ out) {
    int b = blockIdx.x;
    int tid = threadIdx.x, c = tid >> 5, lane = tid & 31;
    __shared__ float sp[DM];
    if (tid < DM) sp[tid] = g_pool[b * DM + tid];
    __syncthreads();
    float acc = 0.f;
    for (int k = lane; k < DM; k += 32) acc += sp[k] * hw[c * DM + k];
#pragma unroll
    for (int o = 16; o > 0; o >>= 1) acc += __shfl_down_sync(0xffffffffu, acc, o);
    if (lane == 0) out[b * NCLS + c] = acc + hb[c];
}

// ---------------- launcher ---------------------------------------------------
extern "C" void kernel_launch(void* const* d_in, const int* in_sizes, int n_in,
                              void* d_out, int out_size) {
    (void)in_sizes; (void)n_in; (void)out_size;
    const float* x        = (const float*)d_in[0];
    const float* in_w     = (const float*)d_in[1];
    const float* in_b     = (const float*)d_in[2];
    const float* lnin_w   = (const float*)d_in[3];
    const float* lnin_b   = (const float*)d_in[4];
    const float* inproj_w = (const float*)d_in[5];
    const float* conv_w   = (const float*)d_in[6];
    const float* conv_b   = (const float*)d_in[7];
    const float* dt_bias  = (const float*)d_in[8];
    const float* A_log    = (const float*)d_in[9];
    const float* Dp       = (const float*)d_in[10];
    const float* norm_w   = (const float*)d_in[11];
    const float* outp_w   = (const float*)d_in[12];
    const float* ln_w     = (const float*)d_in[13];
    const float* ln_b     = (const float*)d_in[14];
    const float* head_w   = (const float*)d_in[15];
    const float* head_b   = (const float*)d_in[16];
    const int*   lengths  = (const int*)d_in[17];
    float* out = (float*)d_out;

    float *ph, *pzx, *py, *pm;
    cudaGetSymbolAddress((void**)&ph,  g_h);
    cudaGetSymbolAddress((void**)&pzx, g_zx);
    cudaGetSymbolAddress((void**)&py,  g_y);
    cudaGetSymbolAddress((void**)&pm,  g_m);

    k_in_ln<<<BLT, 256>>>(x, in_w, in_b, lnin_w, lnin_b);
    for (int i = 0; i < NLAYER; i++) {
        gemm_nt<<<dim3((PRJ + GBN - 1) / GBN, BLT / GBM), 256>>>(
            ph, inproj_w + (size_t)i * PRJ * DM, pzx, BLT, PRJ, DM);
        k_conv<<<(BLT * CCH) / 256, 256>>>(conv_w + i * DCV * CCH, conv_b + i * CCH);
        k_dt<<<(BLT * NHH) / 256, 256>>>(dt_bias + i * NHH, A_log + i * NHH);
        k_scan<<<BB * NHH, 256>>>(Dp + i * NHH);
        k_rms<<<BLT, 256>>>(norm_w + i * DI);
        gemm_nt<<<dim3(DM / GBN, BLT / GBM), 256>>>(
            py, outp_w + (size_t)i * DM * DI, pm, BLT, DM, DI);
        k_addln<<<BLT, 256>>>(ln_w + i * DM, ln_b + i * DM);
    }
    k_pool<<<BB, 256>>>(lengths);
    k_head<<<BB, NCLS * 32>>>(head_w, head_b, out);
}

// round 2
// speedup vs baseline: 1.1566x; 1.1566x over previous
#include <cuda_runtime.h>
#include <math.h>

#define BB 32
#define LL 1024
#define BLT (BB*LL)
#define DIN 63
#define DM 256
#define NCLS 14
#define NLAYER 4
#define DI 512
#define DS 128
#define NHH 8
#define HPP 64
#define DCV 4
#define CCH 768
#define PRJ 1288
#define EPSF 1e-5f

// ---------------- scratch (device globals; no cudaMalloc allowed) ----------
__device__ float g_h[BLT*DM];                 // 33.5 MB residual/stream
__device__ float g_zx[(size_t)BLT*PRJ];       // 168 MB inproj output
__device__ float g_xbc[(size_t)BLT*CCH];      // 100 MB conv+silu output
__device__ float g_dt[BLT*NHH];
__device__ float g_dA[BLT*NHH];
__device__ float g_y[(size_t)BLT*DI];         // 67 MB scan output / rms / gemm A
__device__ float g_m[BLT*DM];                 // 33.5 MB outproj output
__device__ float g_pool[BB*DM];

// ---------------- block layernorm helper (blockDim == 256) -----------------
__device__ __forceinline__ void ln_write256(float acc, float* outp,
                                            const float* __restrict__ w,
                                            const float* __restrict__ b, int j) {
    __shared__ float s1[8], s2[8];
    float v = acc, v2 = acc * acc;
    int lane = j & 31, wp = j >> 5;
#pragma unroll
    for (int o = 16; o > 0; o >>= 1) {
        v  += __shfl_down_sync(0xffffffffu, v,  o);
        v2 += __shfl_down_sync(0xffffffffu, v2, o);
    }
    if (lane == 0) { s1[wp] = v; s2[wp] = v2; }
    __syncthreads();
    if (j == 0) {
        float a = 0.f, c = 0.f;
#pragma unroll
        for (int i = 0; i < 8; i++) { a += s1[i]; c += s2[i]; }
        s1[0] = a * (1.f / DM);
        s2[0] = c * (1.f / DM);
    }
    __syncthreads();
    float mu = s1[0], var = s2[0] - mu * mu;
    outp[j] = (acc - mu) * rsqrtf(var + EPSF) * w[j] + b[j];
}

// ---------------- input projection + layernorm ------------------------------
__global__ __launch_bounds__(256) void k_in_ln(const float* __restrict__ x,
                                               const float* __restrict__ w,
                                               const float* __restrict__ bias,
                                               const float* __restrict__ gw,
                                               const float* __restrict__ gb) {
    int row = blockIdx.x, j = threadIdx.x;
    __shared__ float sx[DIN];
    if (j < DIN) sx[j] = x[(size_t)row * DIN + j];
    __syncthreads();
    const float* wr = w + j * DIN;
    float acc = bias[j];
#pragma unroll
    for (int k = 0; k < DIN; k++) acc += sx[k] * wr[k];
    ln_write256(acc, g_h + (size_t)row * DM, gw, gb, j);
}

// ================= tf32 tensor-core GEMM: C[M,N] = A[M,K] @ B[N,K]^T =======
// Block 128x128x32, 256 threads = 8 warps (2M x 4N), warp tile 64x32.
// SMEM uses k-permutation kp(k) = (k&3)*8 + (k>>2) with 36-float row pitch so
// each mma fragment set (all 4 k-steps) is two conflict-free LDS.128.

__device__ __forceinline__ float to_tf32(float x) {
    asm("cvt.rna.tf32.f32 %0, %0;" : "+f"(x));
    return x;
}

__device__ __forceinline__ void mma8(float* c,
                                     unsigned a0, unsigned a1, unsigned a2, unsigned a3,
                                     unsigned b0, unsigned b1) {
    asm volatile(
        "mma.sync.aligned.m16n8k8.row.col.f32.tf32.tf32.f32 "
        "{%0,%1,%2,%3}, {%4,%5,%6,%7}, {%8,%9}, {%0,%1,%2,%3};"
        : "+f"(c[0]), "+f"(c[1]), "+f"(c[2]), "+f"(c[3])
        : "r"(a0), "r"(a1), "r"(a2), "r"(a3), "r"(b0), "r"(b1));
}

#define TPITCH 36
__global__ __launch_bounds__(256) void gemm_tf32(const float* __restrict__ A,
                                                 const float* __restrict__ B,
                                                 float* __restrict__ C,
                                                 int M, int N, int K) {
    __shared__ __align__(16) float As[128][TPITCH];
    __shared__ __align__(16) float Bs[128][TPITCH];
    int tid = threadIdx.x;
    int bm = blockIdx.y * 128, bn = blockIdx.x * 128;
    int lane = tid & 31, warp = tid >> 5;
    int quad = lane >> 2, tq = lane & 3;
    int wm = (warp & 1) * 64, wn = (warp >> 1) * 32;

    float acc[4][4][4];
#pragma unroll
    for (int i = 0; i < 4; i++)
#pragma unroll
        for (int j = 0; j < 4; j++)
#pragma unroll
            for (int f = 0; f < 4; f++) acc[i][j][f] = 0.f;

    float4 sa[4], sb[4];

    // initial global loads (k0 = 0)
#pragma unroll
    for (int i = 0; i < 4; i++) {
        int idx = i * 256 + tid;
        int r = idx >> 3, c4 = (idx & 7) * 4;
        sa[i] = *(const float4*)(A + (size_t)(bm + r) * K + c4);
        float4 v = make_float4(0.f, 0.f, 0.f, 0.f);
        if (bn + r < N) v = *(const float4*)(B + (size_t)(bn + r) * K + c4);
        sb[i] = v;
    }

    for (int k0 = 0; k0 < K; k0 += 32) {
        __syncthreads();
        // store staged slab with tf32 round + k-permutation
#pragma unroll
        for (int i = 0; i < 4; i++) {
            int idx = i * 256 + tid;
            int r = idx >> 3, j = idx & 7;
            As[r][j]      = to_tf32(sa[i].x);
            As[r][8 + j]  = to_tf32(sa[i].y);
            As[r][16 + j] = to_tf32(sa[i].z);
            As[r][24 + j] = to_tf32(sa[i].w);
            Bs[r][j]      = to_tf32(sb[i].x);
            Bs[r][8 + j]  = to_tf32(sb[i].y);
            Bs[r][16 + j] = to_tf32(sb[i].z);
            Bs[r][24 + j] = to_tf32(sb[i].w);
        }
        __syncthreads();

        // prefetch next slab (overlaps with mma below)
        if (k0 + 32 < K) {
#pragma unroll
            for (int i = 0; i < 4; i++) {
                int idx = i * 256 + tid;
                int r = idx >> 3, c4 = (idx & 7) * 4;
                sa[i] = *(const float4*)(A + (size_t)(bm + r) * K + k0 + 32 + c4);
                float4 v = make_float4(0.f, 0.f, 0.f, 0.f);
                if (bn + r < N) v = *(const float4*)(B + (size_t)(bn + r) * K + k0 + 32 + c4);
                sb[i] = v;
            }
        }

        // load all B fragments for this warp (4 n-tiles x 8 regs)
        unsigned bq[4][8];
#pragma unroll
        for (int j = 0; j < 4; j++) {
            const float* bp = &Bs[wn + j * 8 + quad][tq * 8];
            *(float4*)&bq[j][0] = *(const float4*)bp;
            *(float4*)&bq[j][4] = *(const float4*)(bp + 4);
        }
#pragma unroll
        for (int i = 0; i < 4; i++) {
            unsigned alo[8], ahi[8];
            const float* ap0 = &As[wm + i * 16 + quad][tq * 8];
            const float* ap1 = &As[wm + i * 16 + 8 + quad][tq * 8];
            *(float4*)&alo[0] = *(const float4*)ap0;
            *(float4*)&alo[4] = *(const float4*)(ap0 + 4);
            *(float4*)&ahi[0] = *(const float4*)ap1;
            *(float4*)&ahi[4] = *(const float4*)(ap1 + 4);
#pragma unroll
            for (int s = 0; s < 4; s++)
#pragma unroll
                for (int j = 0; j < 4; j++)
                    mma8(acc[i][j], alo[2 * s], ahi[2 * s], alo[2 * s + 1], ahi[2 * s + 1],
                         bq[j][2 * s], bq[j][2 * s + 1]);
        }
    }

    // store C
#pragma unroll
    for (int i = 0; i < 4; i++) {
        int row = bm + wm + i * 16 + quad;
#pragma unroll
        for (int j = 0; j < 4; j++) {
            int col = bn + wn + j * 8 + tq * 2;
            if (col < N) {
                float2 v0 = make_float2(acc[i][j][0], acc[i][j][1]);
                float2 v1 = make_float2(acc[i][j][2], acc[i][j][3]);
                *(float2*)(C + (size_t)row * N + col) = v0;
                *(float2*)(C + (size_t)(row + 8) * N + col) = v1;
            }
        }
    }
}

// ---------------- causal depthwise conv + silu ------------------------------
__global__ __launch_bounds__(256) void k_conv(const float* __restrict__ cw,
                                              const float* __restrict__ cb) {
    int idx = blockIdx.x * 256 + threadIdx.x;      // BLT*CCH exact multiple
    int c = idx % CCH;
    int row = idx / CCH;
    int t = row & (LL - 1);
    const float* base = g_zx + (size_t)row * PRJ + DI + c;
    float acc = cb[c];
#pragma unroll
    for (int k = 0; k < DCV; k++) {
        int tt = t + k - (DCV - 1);
        if (tt >= 0) acc += base[(long)(k - (DCV - 1)) * PRJ] * cw[k * CCH + c];
    }
    float s = acc / (1.f + expf(-acc));
    g_xbc[(size_t)row * CCH + c] = s;
}

// ---------------- dt = softplus(dt + bias), dA = exp(dt * -exp(A_log)) -----
__global__ __launch_bounds__(256) void k_dt(const float* __restrict__ dtb,
                                            const float* __restrict__ alog) {
    int idx = blockIdx.x * 256 + threadIdx.x;      // BLT*NHH exact multiple
    int row = idx >> 3, hh = idx & 7;
    float v = g_zx[(size_t)row * PRJ + DI + CCH + hh] + dtb[hh];
    float dt = (v > 20.f) ? v : log1pf(expf(v));
    float A = -expf(alog[hh]);
    g_dt[idx] = dt;
    g_dA[idx] = expf(dt * A);
}

// ---------------- sequential SSM scan ---------------------------------------
// one block per (b,h); 256 threads; thread tile 4(p) x 8(n); state in regs.
__global__ __launch_bounds__(256) void k_scan(const float* __restrict__ Dp) {
    int bh = blockIdx.x, b = bh >> 3, hh = bh & 7;
    int tid = threadIdx.x;
    int pg = tid >> 4, ng = tid & 15;
    int p0 = pg * 4, n0 = ng * 8;
    float hs[4][8];
#pragma unroll
    for (int i = 0; i < 4; i++)
#pragma unroll
        for (int j = 0; j < 8; j++) hs[i][j] = 0.f;

    __shared__ __align__(16) float sB[DS], sC[DS], sX[HPP];
    __shared__ float sSc[2];
    float Dh = Dp[hh];
    const float* xrow = g_xbc + (size_t)b * LL * CCH;
    const float* zrow = g_zx + (size_t)b * LL * PRJ + hh * HPP;
    float* yrow = g_y + (size_t)b * LL * DI + hh * HPP;
    const float* dAp = g_dA + (size_t)(b * LL) * NHH + hh;
    const float* dtp = g_dt + (size_t)(b * LL) * NHH + hh;

    for (int t = 0; t < LL; t++) {
        const float* xr = xrow + (size_t)t * CCH;
        if (tid < 128) sB[tid] = xr[DI + tid];
        else           sC[tid - 128] = xr[DI + DS + tid - 128];
        if (tid < 64)  sX[tid] = xr[hh * HPP + tid];
        else if (tid == 64) { sSc[0] = dAp[t * NHH]; sSc[1] = dtp[t * NHH]; }
        __syncthreads();

        float dA = sSc[0], dtv = sSc[1];
        float xv[4], dtx[4], acc[4];
#pragma unroll
        for (int i = 0; i < 4; i++) {
            xv[i] = sX[p0 + i];
            dtx[i] = dtv * xv[i];
            acc[i] = 0.f;
        }
        float bq[8], cq[8];
        *(float4*)&bq[0] = *(const float4*)&sB[n0];
        *(float4*)&bq[4] = *(const float4*)&sB[n0 + 4];
        *(float4*)&cq[0] = *(const float4*)&sC[n0];
        *(float4*)&cq[4] = *(const float4*)&sC[n0 + 4];
#pragma unroll
        for (int i = 0; i < 4; i++)
#pragma unroll
            for (int j = 0; j < 8; j++) {
                hs[i][j] = hs[i][j] * dA + dtx[i] * bq[j];
                acc[i] += hs[i][j] * cq[j];
            }
#pragma unroll
        for (int o = 8; o > 0; o >>= 1)
#pragma unroll
            for (int i = 0; i < 4; i++)
                acc[i] += __shfl_down_sync(0xffffffffu, acc[i], o, 16);
        if (ng == 0) {
#pragma unroll
            for (int i = 0; i < 4; i++) {
                float z = zrow[(size_t)t * PRJ + p0 + i];
                float sz = z / (1.f + expf(-z));
                yrow[(size_t)t * DI + p0 + i] = (acc[i] + Dh * xv[i]) * sz;
            }
        }
        __syncthreads();
    }
}

// ---------------- RMS norm over 512 (in place on g_y) -----------------------
__global__ __launch_bounds__(256) void k_rms(const float* __restrict__ nw) {
    int row = blockIdx.x, j = threadIdx.x;
    float a0 = g_y[(size_t)row * DI + j];
    float a1 = g_y[(size_t)row * DI + 256 + j];
    float v = a0 * a0 + a1 * a1;
    __shared__ float s1[8];
    int lane = j & 31, w = j >> 5;
#pragma unroll
    for (int o = 16; o > 0; o >>= 1) v += __shfl_down_sync(0xffffffffu, v, o);
    if (lane == 0) s1[w] = v;
    __syncthreads();
    if (j == 0) {
        float a = 0.f;
#pragma unroll
        for (int i = 0; i < 8; i++) a += s1[i];
        s1[0] = a * (1.f / DI);
    }
    __syncthreads();
    float sc = rsqrtf(s1[0] + EPSF);
    g_y[(size_t)row * DI + j]       = a0 * sc * nw[j];
    g_y[(size_t)row * DI + 256 + j] = a1 * sc * nw[j + 256];
}

// ---------------- residual add + layernorm (writes g_h) ---------------------
__global__ __launch_bounds__(256) void k_addln(const float* __restrict__ lw,
                                               const float* __restrict__ lb) {
    int row = blockIdx.x, j = threadIdx.x;
    size_t idx = (size_t)row * DM + j;
    float acc = g_m[idx] + g_h[idx];
    ln_write256(acc, g_h + (size_t)row * DM, lw, lb, j);
}

// ---------------- masked mean pool -------------------------------------------
__global__ __launch_bounds__(256) void k_pool(const int* __restrict__ lengths) {
    int b = blockIdx.x, d = threadIdx.x;
    int len = lengths[b];
    float acc = 0.f;
    const float* base = g_h + (size_t)b * LL * DM + d;
#pragma unroll 8
    for (int t = 0; t < len; t++) acc += base[(size_t)t * DM];
    g_pool[b * DM + d] = acc / (float)len;
}

// ---------------- classification head ---------------------------------------
__global__ __launch_bounds__(NCLS*32) void k_head(const float* __restrict__ hw,
                                                  const float* __restrict__ hb,
                                                  float* __restrict__ out) {
    int b = blockIdx.x;
    int tid = threadIdx.x, c = tid >> 5, lane = tid & 31;
    __shared__ float sp[DM];
    if (tid < DM) sp[tid] = g_pool[b * DM + tid];
    __syncthreads();
    float acc = 0.f;
    for (int k = lane; k < DM; k += 32) acc += sp[k] * hw[c * DM + k];
#pragma unroll
    for (int o = 16; o > 0; o >>= 1) acc += __shfl_down_sync(0xffffffffu, acc, o);
    if (lane == 0) out[b * NCLS + c] = acc + hb[c];
}

// ---------------- launcher ---------------------------------------------------
extern "C" void kernel_launch(void* const* d_in, const int* in_sizes, int n_in,
                              void* d_out, int out_size) {
    (void)in_sizes; (void)n_in; (void)out_size;
    const float* x        = (const float*)d_in[0];
    const float* in_w     = (const float*)d_in[1];
    const float* in_b     = (const float*)d_in[2];
    const float* lnin_w   = (const float*)d_in[3];
    const float* lnin_b   = (const float*)d_in[4];
    const float* inproj_w = (const float*)d_in[5];
    const float* conv_w   = (const float*)d_in[6];
    const float* conv_b   = (const float*)d_in[7];
    const float* dt_bias  = (const float*)d_in[8];
    const float* A_log    = (const float*)d_in[9];
    const float* Dp       = (const float*)d_in[10];
    const float* norm_w   = (const float*)d_in[11];
    const float* outp_w   = (const float*)d_in[12];
    const float* ln_w     = (const float*)d_in[13];
    const float* ln_b     = (const float*)d_in[14];
    const float* head_w   = (const float*)d_in[15];
    const float* head_b   = (const float*)d_in[16];
    const int*   lengths  = (const int*)d_in[17];
    float* out = (float*)d_out;

    float *ph, *pzx, *py, *pm;
    cudaGetSymbolAddress((void**)&ph,  g_h);
    cudaGetSymbolAddress((void**)&pzx, g_zx);
    cudaGetSymbolAddress((void**)&py,  g_y);
    cudaGetSymbolAddress((void**)&pm,  g_m);

    k_in_ln<<<BLT, 256>>>(x, in_w, in_b, lnin_w, lnin_b);
    for (int i = 0; i < NLAYER; i++) {
        gemm_tf32<<<dim3((PRJ + 127) / 128, BLT / 128), 256>>>(
            ph, inproj_w + (size_t)i * PRJ * DM, pzx, BLT, PRJ, DM);
        k_conv<<<(BLT * CCH) / 256, 256>>>(conv_w + i * DCV * CCH, conv_b + i * CCH);
        k_dt<<<(BLT * NHH) / 256, 256>>>(dt_bias + i * NHH, A_log + i * NHH);
        k_scan<<<BB * NHH, 256>>>(Dp + i * NHH);
        k_rms<<<BLT, 256>>>(norm_w + i * DI);
        gemm_tf32<<<dim3(DM / 128, BLT / 128), 256>>>(
            py, outp_w + (size_t)i * DM * DI, pm, BLT, DM, DI);
        k_addln<<<BLT, 256>>>(ln_w + i * DM, ln_b + i * DM);
    }
    k_pool<<<BB, 256>>>(lengths);
    k_head<<<BB, NCLS * 32>>>(head_w, head_b, out);
}

// round 3
// speedup vs baseline: 2.0363x; 1.7605x over previous
#include <cuda_runtime.h>
#include <math.h>

#define BB 32
#define LL 1024
#define BLT (BB*LL)
#define DIN 63
#define DM 256
#define NCLS 14
#define NLAYER 4
#define DI 512
#define DS 128
#define NHH 8
#define HPP 64
#define DCV 4
#define CCH 768
#define PRJ 1288
#define EPSF 1e-5f

// ---------------- scratch (device globals; no cudaMalloc allowed) ----------
__device__ float g_h[BLT*DM];                 // residual/stream
__device__ float g_zx[(size_t)BLT*PRJ];       // inproj output
__device__ float g_xbc[(size_t)BLT*CCH];      // conv+silu output
__device__ float g_dt[BLT*NHH];
__device__ float g_dA[BLT*NHH];
__device__ float g_y[(size_t)BLT*DI];         // scan output / rms / gemm A
__device__ float g_m[BLT*DM];                 // outproj output
__device__ float g_poolp[8][BB*DM];           // partial pools

// ---------------- packed f32x2 helpers --------------------------------------
__device__ __forceinline__ unsigned long long pk2(float lo, float hi) {
    unsigned long long r;
    asm("mov.b64 %0, {%1, %2};" : "=l"(r) : "f"(lo), "f"(hi));
    return r;
}
__device__ __forceinline__ void upk2(float& lo, float& hi, unsigned long long v) {
    asm("mov.b64 {%0, %1}, %2;" : "=f"(lo), "=f"(hi) : "l"(v));
}
__device__ __forceinline__ unsigned long long mul2(unsigned long long a, unsigned long long b) {
    unsigned long long r;
    asm("mul.rn.f32x2 %0, %1, %2;" : "=l"(r) : "l"(a), "l"(b));
    return r;
}
__device__ __forceinline__ unsigned long long fma2(unsigned long long a, unsigned long long b,
                                                   unsigned long long c) {
    unsigned long long r;
    asm("fma.rn.f32x2 %0, %1, %2, %3;" : "=l"(r) : "l"(a), "l"(b), "l"(c));
    return r;
}

// ---------------- block layernorm helper (blockDim == 256) -----------------
__device__ __forceinline__ void ln_write256(float acc, float* outp,
                                            const float* __restrict__ w,
                                            const float* __restrict__ b, int j) {
    __shared__ float s1[8], s2[8];
    float v = acc, v2 = acc * acc;
    int lane = j & 31, wp = j >> 5;
#pragma unroll
    for (int o = 16; o > 0; o >>= 1) {
        v  += __shfl_down_sync(0xffffffffu, v,  o);
        v2 += __shfl_down_sync(0xffffffffu, v2, o);
    }
    if (lane == 0) { s1[wp] = v; s2[wp] = v2; }
    __syncthreads();
    if (j == 0) {
        float a = 0.f, c = 0.f;
#pragma unroll
        for (int i = 0; i < 8; i++) { a += s1[i]; c += s2[i]; }
        s1[0] = a * (1.f / DM);
        s2[0] = c * (1.f / DM);
    }
    __syncthreads();
    float mu = s1[0], var = s2[0] - mu * mu;
    outp[j] = (acc - mu) * rsqrtf(var + EPSF) * w[j] + b[j];
}

// ---------------- input projection + layernorm ------------------------------
__global__ __launch_bounds__(256) void k_in_ln(const float* __restrict__ x,
                                               const float* __restrict__ w,
                                               const float* __restrict__ bias,
                                               const float* __restrict__ gw,
                                               const float* __restrict__ gb) {
    int row = blockIdx.x, j = threadIdx.x;
    __shared__ float sx[DIN];
    if (j < DIN) sx[j] = x[(size_t)row * DIN + j];
    __syncthreads();
    const float* wr = w + j * DIN;
    float acc = bias[j];
#pragma unroll
    for (int k = 0; k < DIN; k++) acc += sx[k] * wr[k];
    ln_write256(acc, g_h + (size_t)row * DM, gw, gb, j);
}

// ================= tf32 tensor-core GEMM: C[M,N] = A[M,K] @ B[N,K]^T =======
// Block 128x128x32, 256 threads = 8 warps (2M x 4N), warp tile 64x32.
// Double-buffered smem, one __syncthreads per K-slab.
// SMEM k-permutation kp(k) = (k&3)*8 + (k>>2), 36-float pitch: each mma
// fragment set (all 4 k-steps) = two conflict-free LDS.128.

__device__ __forceinline__ float to_tf32(float x) {
    asm("cvt.rna.tf32.f32 %0, %0;" : "+f"(x));
    return x;
}

__device__ __forceinline__ void mma8(float* c,
                                     unsigned a0, unsigned a1, unsigned a2, unsigned a3,
                                     unsigned b0, unsigned b1) {
    asm volatile(
        "mma.sync.aligned.m16n8k8.row.col.f32.tf32.tf32.f32 "
        "{%0,%1,%2,%3}, {%4,%5,%6,%7}, {%8,%9}, {%0,%1,%2,%3};"
        : "+f"(c[0]), "+f"(c[1]), "+f"(c[2]), "+f"(c[3])
        : "r"(a0), "r"(a1), "r"(a2), "r"(a3), "r"(b0), "r"(b1));
}

#define TPITCH 36
#define GEMM_SMEM (4 * 128 * TPITCH * 4)   // 2 bufs x (A+B) x 128 x 36 floats

__global__ __launch_bounds__(256) void gemm_tf32(const float* __restrict__ A,
                                                 const float* __restrict__ B,
                                                 float* __restrict__ C,
                                                 int M, int N, int K) {
    extern __shared__ float smem_dyn[];
    float (*As)[128][TPITCH] = (float (*)[128][TPITCH])smem_dyn;
    float (*Bs)[128][TPITCH] = (float (*)[128][TPITCH])(smem_dyn + 2 * 128 * TPITCH);

    int tid = threadIdx.x;
    int bm = blockIdx.y * 128, bn = blockIdx.x * 128;
    int lane = tid & 31, warp = tid >> 5;
    int quad = lane >> 2, tq = lane & 3;
    int wm = (warp & 1) * 64, wn = (warp >> 1) * 32;

    float acc[4][4][4];
#pragma unroll
    for (int i = 0; i < 4; i++)
#pragma unroll
        for (int j = 0; j < 4; j++)
#pragma unroll
            for (int f = 0; f < 4; f++) acc[i][j][f] = 0.f;

    float4 sa[4], sb[4];

    // ---- load + store slab 0 ----
#pragma unroll
    for (int i = 0; i < 4; i++) {
        int idx = i * 256 + tid;
        int r = idx >> 3, c4 = (idx & 7) * 4;
        sa[i] = *(const float4*)(A + (size_t)(bm + r) * K + c4);
        float4 v = make_float4(0.f, 0.f, 0.f, 0.f);
        if (bn + r < N) v = *(const float4*)(B + (size_t)(bn + r) * K + c4);
        sb[i] = v;
    }
#pragma unroll
    for (int i = 0; i < 4; i++) {
        int idx = i * 256 + tid;
        int r = idx >> 3, j = idx & 7;
        As[0][r][j]      = to_tf32(sa[i].x);
        As[0][r][8 + j]  = to_tf32(sa[i].y);
        As[0][r][16 + j] = to_tf32(sa[i].z);
        As[0][r][24 + j] = to_tf32(sa[i].w);
        Bs[0][r][j]      = to_tf32(sb[i].x);
        Bs[0][r][8 + j]  = to_tf32(sb[i].y);
        Bs[0][r][16 + j] = to_tf32(sb[i].z);
        Bs[0][r][24 + j] = to_tf32(sb[i].w);
    }
    __syncthreads();

    int nIter = K >> 5;
    for (int it = 0; it < nIter; it++) {
        int cur = it & 1;
        bool more = (it + 1 < nIter);
        // prefetch next slab into registers (overlaps mma below)
        if (more) {
            int k0 = (it + 1) << 5;
#pragma unroll
            for (int i = 0; i < 4; i++) {
                int idx = i * 256 + tid;
                int r = idx >> 3, c4 = (idx & 7) * 4;
                sa[i] = *(const float4*)(A + (size_t)(bm + r) * K + k0 + c4);
                float4 v = make_float4(0.f, 0.f, 0.f, 0.f);
                if (bn + r < N) v = *(const float4*)(B + (size_t)(bn + r) * K + k0 + c4);
                sb[i] = v;
            }
        }

        // ---- mma on buffer cur ----
        unsigned bq[4][8];
#pragma unroll
        for (int j = 0; j < 4; j++) {
            const float* bp = &Bs[cur][wn + j * 8 + quad][tq * 8];
            *(float4*)&bq[j][0] = *(const float4*)bp;
            *(float4*)&bq[j][4] = *(const float4*)(bp + 4);
        }
#pragma unroll
        for (int i = 0; i < 4; i++) {
            unsigned alo[8], ahi[8];
            const float* ap0 = &As[cur][wm + i * 16 + quad][tq * 8];
            const float* ap1 = &As[cur][wm + i * 16 + 8 + quad][tq * 8];
            *(float4*)&alo[0] = *(const float4*)ap0;
            *(float4*)&alo[4] = *(const float4*)(ap0 + 4);
            *(float4*)&ahi[0] = *(const float4*)ap1;
            *(float4*)&ahi[4] = *(const float4*)(ap1 + 4);
#pragma unroll
            for (int s = 0; s < 4; s++)
#pragma unroll
                for (int j = 0; j < 4; j++)
                    mma8(acc[i][j], alo[2 * s], ahi[2 * s], alo[2 * s + 1], ahi[2 * s + 1],
                         bq[j][2 * s], bq[j][2 * s + 1]);
        }

        // ---- store prefetched slab into other buffer ----
        if (more) {
            int nb = cur ^ 1;
#pragma unroll
            for (int i = 0; i < 4; i++) {
                int idx = i * 256 + tid;
                int r = idx >> 3, j = idx & 7;
                As[nb][r][j]      = to_tf32(sa[i].x);
                As[nb][r][8 + j]  = to_tf32(sa[i].y);
                As[nb][r][16 + j] = to_tf32(sa[i].z);
                As[nb][r][24 + j] = to_tf32(sa[i].w);
                Bs[nb][r][j]      = to_tf32(sb[i].x);
                Bs[nb][r][8 + j]  = to_tf32(sb[i].y);
                Bs[nb][r][16 + j] = to_tf32(sb[i].z);
                Bs[nb][r][24 + j] = to_tf32(sb[i].w);
            }
        }
        __syncthreads();
    }

    // store C
#pragma unroll
    for (int i = 0; i < 4; i++) {
        int row = bm + wm + i * 16 + quad;
#pragma unroll
        for (int j = 0; j < 4; j++) {
            int col = bn + wn + j * 8 + tq * 2;
            if (col < N) {
                float2 v0 = make_float2(acc[i][j][0], acc[i][j][1]);
                float2 v1 = make_float2(acc[i][j][2], acc[i][j][3]);
                *(float2*)(C + (size_t)row * N + col) = v0;
                *(float2*)(C + (size_t)(row + 8) * N + col) = v1;
            }
        }
    }
}

// ---------------- causal depthwise conv + silu ------------------------------
__global__ __launch_bounds__(256) void k_conv(const float* __restrict__ cw,
                                              const float* __restrict__ cb) {
    int idx = blockIdx.x * 256 + threadIdx.x;
    int c = idx % CCH;
    int row = idx / CCH;
    int t = row & (LL - 1);
    const float* base = g_zx + (size_t)row * PRJ + DI + c;
    float acc = cb[c];
#pragma unroll
    for (int k = 0; k < DCV; k++) {
        int tt = t + k - (DCV - 1);
        if (tt >= 0) acc += base[(long)(k - (DCV - 1)) * PRJ] * cw[k * CCH + c];
    }
    float s = acc / (1.f + expf(-acc));
    g_xbc[(size_t)row * CCH + c] = s;
}

// ---------------- dt = softplus(dt + bias), dA = exp(dt * -exp(A_log)) -----
__global__ __launch_bounds__(256) void k_dt(const float* __restrict__ dtb,
                                            const float* __restrict__ alog) {
    int idx = blockIdx.x * 256 + threadIdx.x;
    int row = idx >> 3, hh = idx & 7;
    float v = g_zx[(size_t)row * PRJ + DI + CCH + hh] + dtb[hh];
    float dt = (v > 20.f) ? v : log1pf(expf(v));
    float A = -expf(alog[hh]);
    g_dt[idx] = dt;
    g_dA[idx] = expf(dt * A);
}

// ---------------- sequential SSM scan (barrier-free, f32x2) ------------------
// one block per (b,h); 256 threads; thread tile 4(p) x 8(n) with n packed in
// f32x2 pairs. No smem, no __syncthreads: every thread loads its operands
// directly (L1 broadcast handles intra-warp redundancy), next timestep
// prefetched into registers during compute.
__global__ __launch_bounds__(256) void k_scan(const float* __restrict__ Dp) {
    int bh = blockIdx.x, b = bh >> 3, hh = bh & 7;
    int tid = threadIdx.x;
    int pg = tid >> 4, ng = tid & 15;
    int p0 = pg * 4, n0 = ng * 8;

    unsigned long long hs[4][4];
#pragma unroll
    for (int i = 0; i < 4; i++)
#pragma unroll
        for (int j = 0; j < 4; j++) hs[i][j] = 0ull;

    const float* Bp  = g_xbc + (size_t)b * LL * CCH + DI + n0;
    const float* Cp  = Bp + DS;
    const float* Xp  = g_xbc + (size_t)b * LL * CCH + hh * HPP + p0;
    const float* dApt = g_dA + (size_t)b * LL * NHH + hh;
    const float* dtpt = g_dt + (size_t)b * LL * NHH + hh;
    const float* Zp  = g_zx + (size_t)b * LL * PRJ + hh * HPP + p0;
    float* Yp = g_y + (size_t)b * LL * DI + hh * HPP + p0;
    float Dh = Dp[hh];

    // prefetch t = 0
    float4 pb0 = *(const float4*)Bp,  pb1 = *(const float4*)(Bp + 4);
    float4 pc0 = *(const float4*)Cp,  pc1 = *(const float4*)(Cp + 4);
    float4 px  = *(const float4*)Xp;
    float pdA = *dApt, pdt = *dtpt;
    float4 pz = make_float4(0.f, 0.f, 0.f, 0.f);
    if (ng == 0) pz = *(const float4*)Zp;

    for (int t = 0; t < LL; t++) {
        float4 vb0 = pb0, vb1 = pb1, vc0 = pc0, vc1 = pc1, vx = px, vz = pz;
        float vdA = pdA, vdt = pdt;
        if (t + 1 < LL) {
            const float* nb = Bp + (size_t)(t + 1) * CCH;
            pb0 = *(const float4*)nb;
            pb1 = *(const float4*)(nb + 4);
            const float* nc = Cp + (size_t)(t + 1) * CCH;
            pc0 = *(const float4*)nc;
            pc1 = *(const float4*)(nc + 4);
            px = *(const float4*)(Xp + (size_t)(t + 1) * CCH);
            pdA = dApt[(size_t)(t + 1) * NHH];
            pdt = dtpt[(size_t)(t + 1) * NHH];
            if (ng == 0) pz = *(const float4*)(Zp + (size_t)(t + 1) * PRJ);
        }

        unsigned long long dA2 = pk2(vdA, vdA);
        float xa[4] = {vx.x, vx.y, vx.z, vx.w};
        unsigned long long bp[4], cp[4], dtx2[4], accp[4];
        bp[0] = pk2(vb0.x, vb0.y); bp[1] = pk2(vb0.z, vb0.w);
        bp[2] = pk2(vb1.x, vb1.y); bp[3] = pk2(vb1.z, vb1.w);
        cp[0] = pk2(vc0.x, vc0.y); cp[1] = pk2(vc0.z, vc0.w);
        cp[2] = pk2(vc1.x, vc1.y); cp[3] = pk2(vc1.z, vc1.w);
#pragma unroll
        for (int i = 0; i < 4; i++) {
            float d = vdt * xa[i];
            dtx2[i] = pk2(d, d);
            accp[i] = 0ull;
        }
#pragma unroll
        for (int i = 0; i < 4; i++)
#pragma unroll
            for (int j = 0; j < 4; j++) {
                hs[i][j] = fma2(dtx2[i], bp[j], mul2(hs[i][j], dA2));
                accp[i] = fma2(hs[i][j], cp[j], accp[i]);
            }
        float acc[4];
#pragma unroll
        for (int i = 0; i < 4; i++) {
            float lo, hi;
            upk2(lo, hi, accp[i]);
            acc[i] = lo + hi;
        }
#pragma unroll
        for (int o = 8; o > 0; o >>= 1)
#pragma unroll
            for (int i = 0; i < 4; i++)
                acc[i] += __shfl_down_sync(0xffffffffu, acc[i], o, 16);
        if (ng == 0) {
            float za[4] = {vz.x, vz.y, vz.z, vz.w};
            float4 yo;
            float* yv = &yo.x;
#pragma unroll
            for (int i = 0; i < 4; i++) {
                float sz = za[i] / (1.f + expf(-za[i]));
                yv[i] = (acc[i] + Dh * xa[i]) * sz;
            }
            *(float4*)(Yp + (size_t)t * DI) = yo;
        }
    }
}

// ---------------- RMS norm over 512 (in place on g_y) -----------------------
__global__ __launch_bounds__(256) void k_rms(const float* __restrict__ nw) {
    int row = blockIdx.x, j = threadIdx.x;
    float a0 = g_y[(size_t)row * DI + j];
    float a1 = g_y[(size_t)row * DI + 256 + j];
    float v = a0 * a0 + a1 * a1;
    __shared__ float s1[8];
    int lane = j & 31, w = j >> 5;
#pragma unroll
    for (int o = 16; o > 0; o >>= 1) v += __shfl_down_sync(0xffffffffu, v, o);
    if (lane == 0) s1[w] = v;
    __syncthreads();
    if (j == 0) {
        float a = 0.f;
#pragma unroll
        for (int i = 0; i < 8; i++) a += s1[i];
        s1[0] = a * (1.f / DI);
    }
    __syncthreads();
    float sc = rsqrtf(s1[0] + EPSF);
    g_y[(size_t)row * DI + j]       = a0 * sc * nw[j];
    g_y[(size_t)row * DI + 256 + j] = a1 * sc * nw[j + 256];
}

// ---------------- residual add + layernorm (writes g_h) ---------------------
__global__ __launch_bounds__(256) void k_addln(const float* __restrict__ lw,
                                               const float* __restrict__ lb) {
    int row = blockIdx.x, j = threadIdx.x;
    size_t idx = (size_t)row * DM + j;
    float acc = g_m[idx] + g_h[idx];
    ln_write256(acc, g_h + (size_t)row * DM, lw, lb, j);
}

// ---------------- masked mean pool (partial sums over 8 t-slices) ----------
__global__ __launch_bounds__(256) void k_pool(const int* __restrict__ lengths) {
    int b = blockIdx.x, s = blockIdx.y, d = threadIdx.x;
    int len = lengths[b];
    int t0 = s * 128;
    int t1 = min(t0 + 128, len);
    float acc = 0.f;
    const float* base = g_h + ((size_t)b * LL + t0) * DM + d;
#pragma unroll 4
    for (int t = t0; t < t1; t++, base += DM) acc += *base;
    g_poolp[s][b * DM + d] = acc;
}

// ---------------- classification head ---------------------------------------
__global__ __launch_bounds__(NCLS*32) void k_head(const float* __restrict__ hw,
                                                  const float* __restrict__ hb,
                                                  const int* __restrict__ lengths,
                                                  float* __restrict__ out) {
    int b = blockIdx.x;
    int tid = threadIdx.x, c = tid >> 5, lane = tid & 31;
    __shared__ float sp[DM];
    if (tid < DM) {
        float a = 0.f;
#pragma unroll
        for (int s = 0; s < 8; s++) a += g_poolp[s][b * DM + tid];
        sp[tid] = a / (float)lengths[b];
    }
    __syncthreads();
    float acc = 0.f;
    for (int k = lane; k < DM; k += 32) acc += sp[k] * hw[c * DM + k];
#pragma unroll
    for (int o = 16; o > 0; o >>= 1) acc += __shfl_down_sync(0xffffffffu, acc, o);
    if (lane == 0) out[b * NCLS + c] = acc + hb[c];
}

// ---------------- launcher ---------------------------------------------------
extern "C" void kernel_launch(void* const* d_in, const int* in_sizes, int n_in,
                              void* d_out, int out_size) {
    (void)in_sizes; (void)n_in; (void)out_size;
    const float* x        = (const float*)d_in[0];
    const float* in_w     = (const float*)d_in[1];
    const float* in_b     = (const float*)d_in[2];
    const float* lnin_w   = (const float*)d_in[3];
    const float* lnin_b   = (const float*)d_in[4];
    const float* inproj_w = (const float*)d_in[5];
    const float* conv_w   = (const float*)d_in[6];
    const float* conv_b   = (const float*)d_in[7];
    const float* dt_bias  = (const float*)d_in[8];
    const float* A_log    = (const float*)d_in[9];
    const float* Dp       = (const float*)d_in[10];
    const float* norm_w   = (const float*)d_in[11];
    const float* outp_w   = (const float*)d_in[12];
    const float* ln_w     = (const float*)d_in[13];
    const float* ln_b     = (const float*)d_in[14];
    const float* head_w   = (const float*)d_in[15];
    const float* head_b   = (const float*)d_in[16];
    const int*   lengths  = (const int*)d_in[17];
    float* out = (float*)d_out;

    float *ph, *pzx, *py, *pm;
    cudaGetSymbolAddress((void**)&ph,  g_h);
    cudaGetSymbolAddress((void**)&pzx, g_zx);
    cudaGetSymbolAddress((void**)&py,  g_y);
    cudaGetSymbolAddress((void**)&pm,  g_m);

    cudaFuncSetAttribute(gemm_tf32, cudaFuncAttributeMaxDynamicSharedMemorySize,
                         GEMM_SMEM);

    k_in_ln<<<BLT, 256>>>(x, in_w, in_b, lnin_w, lnin_b);
    for (int i = 0; i < NLAYER; i++) {
        gemm_tf32<<<dim3((PRJ + 127) / 128, BLT / 128), 256, GEMM_SMEM>>>(
            ph, inproj_w + (size_t)i * PRJ * DM, pzx, BLT, PRJ, DM);
        k_conv<<<(BLT * CCH) / 256, 256>>>(conv_w + i * DCV * CCH, conv_b + i * CCH);
        k_dt<<<(BLT * NHH) / 256, 256>>>(dt_bias + i * NHH, A_log + i * NHH);
        k_scan<<<BB * NHH, 256>>>(Dp + i * NHH);
        k_rms<<<BLT, 256>>>(norm_w + i * DI);
        gemm_tf32<<<dim3(DM / 128, BLT / 128), 256, GEMM_SMEM>>>(
            py, outp_w + (size_t)i * DM * DI, pm, BLT, DM, DI);
        k_addln<<<BLT, 256>>>(ln_w + i * DM, ln_b + i * DM);
    }
    k_pool<<<dim3(BB, 8), 256>>>(lengths);
    k_head<<<BB, NCLS * 32>>>(head_w, head_b, lengths, out);
}

// round 4
// speedup vs baseline: 2.1421x; 1.0520x over previous
#include <cuda_runtime.h>
#include <math.h>

#define BB 32
#define LL 1024
#define BLT (BB*LL)
#define DIN 63
#define DM 256
#define NCLS 14
#define NLAYER 4
#define DI 512
#define DS 128
#define NHH 8
#define HPP 64
#define DCV 4
#define CCH 768
#define PRJ 1288
#define EPSF 1e-5f

// ---------------- scratch (device globals; no cudaMalloc allowed) ----------
__device__ float g_h[BLT*DM];                 // residual/stream (k-permuted cols)
__device__ float g_zx[(size_t)BLT*PRJ];       // inproj output (logical cols)
__device__ float g_xbc[(size_t)BLT*CCH];      // conv+silu output
__device__ float g_dt[BLT*NHH];
__device__ float g_dA[BLT*NHH];
__device__ float g_y[(size_t)BLT*DI];         // scan out (logical) -> rms (permuted+tf32)
__device__ float g_m[BLT*DM];                 // outproj output (logical cols)
__device__ float g_poolp[8][BB*DM];           // partial pools (permuted cols)
__device__ float g_win[(size_t)NLAYER*PRJ*DM];   // permuted+rounded inproj weights
__device__ float g_wout[(size_t)NLAYER*DM*DI];   // permuted+rounded outproj weights

// ---------------- column permutation: kp within 32-groups -------------------
// kp(k) = (k&3)*8 + (k>>2)  (bijection on 0..31); P groups of 32.
__device__ __forceinline__ int permc(int j) {
    return (j & ~31) | (((j & 3) << 3) | ((j & 31) >> 2));
}
__device__ __forceinline__ int permcinv(int j) {
    return (j & ~31) | (((j & 7) << 2) | ((j & 31) >> 3));
}

__device__ __forceinline__ float to_tf32(float x) {
    asm("cvt.rna.tf32.f32 %0, %0;" : "+f"(x));
    return x;
}

// ---------------- packed f32x2 helpers --------------------------------------
__device__ __forceinline__ unsigned long long pk2(float lo, float hi) {
    unsigned long long r;
    asm("mov.b64 %0, {%1, %2};" : "=l"(r) : "f"(lo), "f"(hi));
    return r;
}
__device__ __forceinline__ void upk2(float& lo, float& hi, unsigned long long v) {
    asm("mov.b64 {%0, %1}, %2;" : "=f"(lo), "=f"(hi) : "l"(v));
}
__device__ __forceinline__ unsigned long long mul2(unsigned long long a, unsigned long long b) {
    unsigned long long r;
    asm("mul.rn.f32x2 %0, %1, %2;" : "=l"(r) : "l"(a), "l"(b));
    return r;
}
__device__ __forceinline__ unsigned long long fma2(unsigned long long a, unsigned long long b,
                                                   unsigned long long c) {
    unsigned long long r;
    asm("fma.rn.f32x2 %0, %1, %2, %3;" : "=l"(r) : "l"(a), "l"(b), "l"(c));
    return r;
}

// ---------------- cp.async helpers ------------------------------------------
__device__ __forceinline__ void cp16(void* dst, const void* src, bool v) {
    unsigned d = (unsigned)__cvta_generic_to_shared(dst);
    int sz = v ? 16 : 0;
    asm volatile("cp.async.ca.shared.global [%0], [%1], 16, %2;"
                 :: "r"(d), "l"(src), "r"(sz) : "memory");
}

// ---------------- weight permute + tf32 round pre-pass ----------------------
__global__ __launch_bounds__(256) void k_permw(const float* __restrict__ W,
                                               float* __restrict__ Wp,
                                               int total, int Kmask) {
    int i = blockIdx.x * 256 + threadIdx.x;
    if (i >= total) return;
    int k = i & Kmask;                 // K power of two
    Wp[(i - k) + permc(k)] = to_tf32(W[i]);
}

// ---------------- block layernorm helper (blockDim == 256) -----------------
// writes LN output for logical col j at PERMUTED position permc(j)
__device__ __forceinline__ void ln_write256(float acc, float* outp,
                                            const float* __restrict__ w,
                                            const float* __restrict__ b, int j) {
    __shared__ float s1[8], s2[8];
    float v = acc, v2 = acc * acc;
    int lane = j & 31, wp = j >> 5;
#pragma unroll
    for (int o = 16; o > 0; o >>= 1) {
        v  += __shfl_down_sync(0xffffffffu, v,  o);
        v2 += __shfl_down_sync(0xffffffffu, v2, o);
    }
    if (lane == 0) { s1[wp] = v; s2[wp] = v2; }
    __syncthreads();
    if (j == 0) {
        float a = 0.f, c = 0.f;
#pragma unroll
        for (int i = 0; i < 8; i++) { a += s1[i]; c += s2[i]; }
        s1[0] = a * (1.f / DM);
        s2[0] = c * (1.f / DM);
    }
    __syncthreads();
    float mu = s1[0], var = s2[0] - mu * mu;
    outp[permc(j)] = (acc - mu) * rsqrtf(var + EPSF) * w[j] + b[j];
}

// ---------------- input projection + layernorm ------------------------------
__global__ __launch_bounds__(256) void k_in_ln(const float* __restrict__ x,
                                               const float* __restrict__ w,
                                               const float* __restrict__ bias,
                                               const float* __restrict__ gw,
                                               const float* __restrict__ gb) {
    int row = blockIdx.x, j = threadIdx.x;
    __shared__ float sx[DIN];
    if (j < DIN) sx[j] = x[(size_t)row * DIN + j];
    __syncthreads();
    const float* wr = w + j * DIN;
    float acc = bias[j];
#pragma unroll
    for (int k = 0; k < DIN; k++) acc += sx[k] * wr[k];
    ln_write256(acc, g_h + (size_t)row * DM, gw, gb, j);
}

// ================= tf32 tensor-core GEMM: C[M,N] = A[M,K] @ B[N,K]^T =======
// A, B are stored COLUMN-PERMUTED in global (kp within 32-groups), B also
// pre-rounded to tf32. Smem slabs are verbatim copies (cp.async), so every
// mma fragment set (4 k-steps) = two conflict-light LDS.128.
// CVTA=true: A is raw fp32 -> LDG + cvt.rna.tf32 + STS.128.
// Block 128x128x32, 256 threads = 8 warps (2M x 4N), 2-stage cp.async pipe.

__device__ __forceinline__ void mma8(float* c,
                                     unsigned a0, unsigned a1, unsigned a2, unsigned a3,
                                     unsigned b0, unsigned b1) {
    asm volatile(
        "mma.sync.aligned.m16n8k8.row.col.f32.tf32.tf32.f32 "
        "{%0,%1,%2,%3}, {%4,%5,%6,%7}, {%8,%9}, {%0,%1,%2,%3};"
        : "+f"(c[0]), "+f"(c[1]), "+f"(c[2]), "+f"(c[3])
        : "r"(a0), "r"(a1), "r"(a2), "r"(a3), "r"(b0), "r"(b1));
}

#define TPITCH 36
#define GEMM_SMEM (4 * 128 * TPITCH * 4)   // 2 bufs x (A+B) x 128 x 36 floats

template<bool CVTA>
__global__ __launch_bounds__(256, 2) void gemm_tf32(const float* __restrict__ A,
                                                    const float* __restrict__ B,
                                                    float* __restrict__ C,
                                                    int M, int N, int K) {
    extern __shared__ float smem_dyn[];
    float (*As)[128][TPITCH] = (float (*)[128][TPITCH])smem_dyn;
    float (*Bs)[128][TPITCH] = (float (*)[128][TPITCH])(smem_dyn + 2 * 128 * TPITCH);

    int tid = threadIdx.x;
    int bm = blockIdx.y * 128, bn = blockIdx.x * 128;
    int lane = tid & 31, warp = tid >> 5;
    int quad = lane >> 2, tq = lane & 3;
    int wm = (warp & 1) * 64, wn = (warp >> 1) * 32;
    int rr = tid >> 3, cc = tid & 7;          // loader: 4 rows (rr+32i), col cc*4

    float acc[4][4][4];
#pragma unroll
    for (int i = 0; i < 4; i++)
#pragma unroll
        for (int j = 0; j < 4; j++)
#pragma unroll
            for (int f = 0; f < 4; f++) acc[i][j][f] = 0.f;

    // ---- issue slab 0 ----
#pragma unroll
    for (int i = 0; i < 4; i++) {
        int r = rr + i * 32;
        cp16(&Bs[0][r][cc * 4], B + (size_t)(bn + r) * K + cc * 4, bn + r < N);
        if (!CVTA)
            cp16(&As[0][r][cc * 4], A + (size_t)(bm + r) * K + cc * 4, true);
    }
    asm volatile("cp.async.commit_group;" ::: "memory");
    if (CVTA) {
#pragma unroll
        for (int i = 0; i < 4; i++) {
            float4 v = *(const float4*)(A + (size_t)(bm + rr + i * 32) * K + cc * 4);
            v.x = to_tf32(v.x); v.y = to_tf32(v.y);
            v.z = to_tf32(v.z); v.w = to_tf32(v.w);
            *(float4*)&As[0][rr + i * 32][cc * 4] = v;
        }
    }

    int nIter = K >> 5;
    for (int it = 0; it < nIter; it++) {
        int cur = it & 1, nb = cur ^ 1;
        bool more = (it + 1 < nIter);

        asm volatile("cp.async.wait_group 0;" ::: "memory");
        __syncthreads();

        // issue next slab (after barrier: prev readers of nb are done)
        if (more) {
            int k0 = (it + 1) << 5;
#pragma unroll
            for (int i = 0; i < 4; i++) {
                int r = rr + i * 32;
                cp16(&Bs[nb][r][cc * 4], B + (size_t)(bn + r) * K + k0 + cc * 4,
                     bn + r < N);
                if (!CVTA)
                    cp16(&As[nb][r][cc * 4], A + (size_t)(bm + r) * K + k0 + cc * 4,
                         true);
            }
            asm volatile("cp.async.commit_group;" ::: "memory");
        }

        // ---- mma on buffer cur ----
#pragma unroll
        for (int i = 0; i < 4; i++) {
            __align__(16) unsigned alo[8], ahi[8];
            const float* ap0 = &As[cur][wm + i * 16 + quad][tq * 8];
            const float* ap1 = &As[cur][wm + i * 16 + 8 + quad][tq * 8];
            *(float4*)&alo[0] = *(const float4*)ap0;
            *(float4*)&alo[4] = *(const float4*)(ap0 + 4);
            *(float4*)&ahi[0] = *(const float4*)ap1;
            *(float4*)&ahi[4] = *(const float4*)(ap1 + 4);
#pragma unroll
            for (int j = 0; j < 4; j++) {
                __align__(16) unsigned bq[8];
                const float* bp = &Bs[cur][wn + j * 8 + quad][tq * 8];
                *(float4*)&bq[0] = *(const float4*)bp;
                *(float4*)&bq[4] = *(const float4*)(bp + 4);
#pragma unroll
                for (int s = 0; s < 4; s++)
                    mma8(acc[i][j], alo[2 * s], ahi[2 * s], alo[2 * s + 1],
                         ahi[2 * s + 1], bq[2 * s], bq[2 * s + 1]);
            }
        }

        // A path for next slab (LDG latency hidden by other warps' mma)
        if (CVTA && more) {
            int k0 = (it + 1) << 5;
#pragma unroll
            for (int i = 0; i < 4; i++) {
                float4 v = *(const float4*)(A + (size_t)(bm + rr + i * 32) * K + k0 + cc * 4);
                v.x = to_tf32(v.x); v.y = to_tf32(v.y);
                v.z = to_tf32(v.z); v.w = to_tf32(v.w);
                *(float4*)&As[nb][rr + i * 32][cc * 4] = v;
            }
        }
    }

    // store C (logical columns)
#pragma unroll
    for (int i = 0; i < 4; i++) {
        int row = bm + wm + i * 16 + quad;
#pragma unroll
        for (int j = 0; j < 4; j++) {
            int col = bn + wn + j * 8 + tq * 2;
            if (col < N) {
                float2 v0 = make_float2(acc[i][j][0], acc[i][j][1]);
                float2 v1 = make_float2(acc[i][j][2], acc[i][j][3]);
                *(float2*)(C + (size_t)row * N + col) = v0;
                *(float2*)(C + (size_t)(row + 8) * N + col) = v1;
            }
        }
    }
}

// ---------------- causal depthwise conv + silu ------------------------------
__global__ __launch_bounds__(256) void k_conv(const float* __restrict__ cw,
                                              const float* __restrict__ cb) {
    int idx = blockIdx.x * 256 + threadIdx.x;
    int c = idx % CCH;
    int row = idx / CCH;
    int t = row & (LL - 1);
    const float* base = g_zx + (size_t)row * PRJ + DI + c;
    float acc = cb[c];
#pragma unroll
    for (int k = 0; k < DCV; k++) {
        int tt = t + k - (DCV - 1);
        if (tt >= 0) acc += base[(long)(k - (DCV - 1)) * PRJ] * cw[k * CCH + c];
    }
    float s = acc / (1.f + expf(-acc));
    g_xbc[(size_t)row * CCH + c] = s;
}

// ---------------- dt = softplus(dt + bias), dA = exp(dt * -exp(A_log)) -----
__global__ __launch_bounds__(256) void k_dt(const float* __restrict__ dtb,
                                            const float* __restrict__ alog) {
    int idx = blockIdx.x * 256 + threadIdx.x;
    int row = idx >> 3, hh = idx & 7;
    float v = g_zx[(size_t)row * PRJ + DI + CCH + hh] + dtb[hh];
    float dt = (v > 20.f) ? v : log1pf(expf(v));
    float A = -expf(alog[hh]);
    g_dt[idx] = dt;
    g_dA[idx] = expf(dt * A);
}

// ---------------- sequential SSM scan (barrier-free, f32x2) ------------------
__global__ __launch_bounds__(256) void k_scan(const float* __restrict__ Dp) {
    int bh = blockIdx.x, b = bh >> 3, hh = bh & 7;
    int tid = threadIdx.x;
    int pg = tid >> 4, ng = tid & 15;
    int p0 = pg * 4, n0 = ng * 8;

    unsigned long long hs[4][4];
#pragma unroll
    for (int i = 0; i < 4; i++)
#pragma unroll
        for (int j = 0; j < 4; j++) hs[i][j] = 0ull;

    const float* Bp  = g_xbc + (size_t)b * LL * CCH + DI + n0;
    const float* Cp  = Bp + DS;
    const float* Xp  = g_xbc + (size_t)b * LL * CCH + hh * HPP + p0;
    const float* dApt = g_dA + (size_t)b * LL * NHH + hh;
    const float* dtpt = g_dt + (size_t)b * LL * NHH + hh;
    const float* Zp  = g_zx + (size_t)b * LL * PRJ + hh * HPP + p0;
    float* Yp = g_y + (size_t)b * LL * DI + hh * HPP + p0;
    float Dh = Dp[hh];

    float4 pb0 = *(const float4*)Bp,  pb1 = *(const float4*)(Bp + 4);
    float4 pc0 = *(const float4*)Cp,  pc1 = *(const float4*)(Cp + 4);
    float4 px  = *(const float4*)Xp;
    float pdA = *dApt, pdt = *dtpt;
    float4 pz = make_float4(0.f, 0.f, 0.f, 0.f);
    if (ng == 0) pz = *(const float4*)Zp;

    for (int t = 0; t < LL; t++) {
        float4 vb0 = pb0, vb1 = pb1, vc0 = pc0, vc1 = pc1, vx = px, vz = pz;
        float vdA = pdA, vdt = pdt;
        if (t + 1 < LL) {
            const float* nb = Bp + (size_t)(t + 1) * CCH;
            pb0 = *(const float4*)nb;
            pb1 = *(const float4*)(nb + 4);
            const float* nc = Cp + (size_t)(t + 1) * CCH;
            pc0 = *(const float4*)nc;
            pc1 = *(const float4*)(nc + 4);
            px = *(const float4*)(Xp + (size_t)(t + 1) * CCH);
            pdA = dApt[(size_t)(t + 1) * NHH];
            pdt = dtpt[(size_t)(t + 1) * NHH];
            if (ng == 0) pz = *(const float4*)(Zp + (size_t)(t + 1) * PRJ);
        }

        unsigned long long dA2 = pk2(vdA, vdA);
        float xa[4] = {vx.x, vx.y, vx.z, vx.w};
        unsigned long long bp[4], cp[4], dtx2[4], accp[4];
        bp[0] = pk2(vb0.x, vb0.y); bp[1] = pk2(vb0.z, vb0.w);
        bp[2] = pk2(vb1.x, vb1.y); bp[3] = pk2(vb1.z, vb1.w);
        cp[0] = pk2(vc0.x, vc0.y); cp[1] = pk2(vc0.z, vc0.w);
        cp[2] = pk2(vc1.x, vc1.y); cp[3] = pk2(vc1.z, vc1.w);
#pragma unroll
        for (int i = 0; i < 4; i++) {
            float d = vdt * xa[i];
            dtx2[i] = pk2(d, d);
            accp[i] = 0ull;
        }
#pragma unroll
        for (int i = 0; i < 4; i++)
#pragma unroll
            for (int j = 0; j < 4; j++) {
                hs[i][j] = fma2(dtx2[i], bp[j], mul2(hs[i][j], dA2));
                accp[i] = fma2(hs[i][j], cp[j], accp[i]);
            }
        float acc[4];
#pragma unroll
        for (int i = 0; i < 4; i++) {
            float lo, hi;
            upk2(lo, hi, accp[i]);
            acc[i] = lo + hi;
        }
#pragma unroll
        for (int o = 8; o > 0; o >>= 1)
#pragma unroll
            for (int i = 0; i < 4; i++)
                acc[i] += __shfl_down_sync(0xffffffffu, acc[i], o, 16);
        if (ng == 0) {
            float za[4] = {vz.x, vz.y, vz.z, vz.w};
            float4 yo;
            float* yv = &yo.x;
#pragma unroll
            for (int i = 0; i < 4; i++) {
                float sz = za[i] / (1.f + expf(-za[i]));
                yv[i] = (acc[i] + Dh * xa[i]) * sz;
            }
            *(float4*)(Yp + (size_t)t * DI) = yo;
        }
    }
}

// ---------------- RMS norm over 512 (in place; writes permuted + tf32) -----
__global__ __launch_bounds__(256) void k_rms(const float* __restrict__ nw) {
    int row = blockIdx.x, j = threadIdx.x;
    float a0 = g_y[(size_t)row * DI + j];
    float a1 = g_y[(size_t)row * DI + 256 + j];
    float v = a0 * a0 + a1 * a1;
    __shared__ float s1[8];
    int lane = j & 31, w = j >> 5;
#pragma unroll
    for (int o = 16; o > 0; o >>= 1) v += __shfl_down_sync(0xffffffffu, v, o);
    if (lane == 0) s1[w] = v;
    __syncthreads();
    if (j == 0) {
        float a = 0.f;
#pragma unroll
        for (int i = 0; i < 8; i++) a += s1[i];
        s1[0] = a * (1.f / DI);
    }
    __syncthreads();
    float sc = rsqrtf(s1[0] + EPSF);
    int pj = permc(j);
    g_y[(size_t)row * DI + pj]       = to_tf32(a0 * sc * nw[j]);
    g_y[(size_t)row * DI + 256 + pj] = to_tf32(a1 * sc * nw[j + 256]);
}

// ---------------- residual add + layernorm (g_h permuted in/out) ------------
__global__ __launch_bounds__(256) void k_addln(const float* __restrict__ lw,
                                               const float* __restrict__ lb) {
    int row = blockIdx.x, j = threadIdx.x;
    float acc = g_m[(size_t)row * DM + j] + g_h[(size_t)row * DM + permc(j)];
    ln_write256(acc, g_h + (size_t)row * DM, lw, lb, j);
}

// ---------------- masked mean pool (permuted cols, 8 t-slices) --------------
__global__ __launch_bounds__(256) void k_pool(const int* __restrict__ lengths) {
    int b = blockIdx.x, s = blockIdx.y, d = threadIdx.x;
    int len = lengths[b];
    int t0 = s * 128;
    int t1 = min(t0 + 128, len);
    float acc = 0.f;
    const float* base = g_h + ((size_t)b * LL + t0) * DM + d;
#pragma unroll 4
    for (int t = t0; t < t1; t++, base += DM) acc += *base;
    g_poolp[s][b * DM + d] = acc;
}

// ---------------- classification head ---------------------------------------
__global__ __launch_bounds__(NCLS*32) void k_head(const float* __restrict__ hw,
                                                  const float* __restrict__ hb,
                                                  const int* __restrict__ lengths,
                                                  float* __restrict__ out) {
    int b = blockIdx.x;
    int tid = threadIdx.x, c = tid >> 5, lane = tid & 31;
    __shared__ float sp[DM];
    if (tid < DM) {
        float a = 0.f;
#pragma unroll
        for (int s = 0; s < 8; s++) a += g_poolp[s][b * DM + tid];
        sp[permcinv(tid)] = a / (float)lengths[b];   // back to logical cols
    }
    __syncthreads();
    float acc = 0.f;
    for (int k = lane; k < DM; k += 32) acc += sp[k] * hw[c * DM + k];
#pragma unroll
    for (int o = 16; o > 0; o >>= 1) acc += __shfl_down_sync(0xffffffffu, acc, o);
    if (lane == 0) out[b * NCLS + c] = acc + hb[c];
}

// ---------------- launcher ---------------------------------------------------
extern "C" void kernel_launch(void* const* d_in, const int* in_sizes, int n_in,
                              void* d_out, int out_size) {
    (void)in_sizes; (void)n_in; (void)out_size;
    const float* x        = (const float*)d_in[0];
    const float* in_w     = (const float*)d_in[1];
    const float* in_b     = (const float*)d_in[2];
    const float* lnin_w   = (const float*)d_in[3];
    const float* lnin_b   = (const float*)d_in[4];
    const float* inproj_w = (const float*)d_in[5];
    const float* conv_w   = (const float*)d_in[6];
    const float* conv_b   = (const float*)d_in[7];
    const float* dt_bias  = (const float*)d_in[8];
    const float* A_log    = (const float*)d_in[9];
    const float* Dp       = (const float*)d_in[10];
    const float* norm_w   = (const float*)d_in[11];
    const float* outp_w   = (const float*)d_in[12];
    const float* ln_w     = (const float*)d_in[13];
    const float* ln_b     = (const float*)d_in[14];
    const float* head_w   = (const float*)d_in[15];
    const float* head_b   = (const float*)d_in[16];
    const int*   lengths  = (const int*)d_in[17];
    float* out = (float*)d_out;

    float *ph, *pzx, *py, *pm, *pwin, *pwout;
    cudaGetSymbolAddress((void**)&ph,    g_h);
    cudaGetSymbolAddress((void**)&pzx,   g_zx);
    cudaGetSymbolAddress((void**)&py,    g_y);
    cudaGetSymbolAddress((void**)&pm,    g_m);
    cudaGetSymbolAddress((void**)&pwin,  g_win);
    cudaGetSymbolAddress((void**)&pwout, g_wout);

    cudaFuncSetAttribute(gemm_tf32<true>,  cudaFuncAttributeMaxDynamicSharedMemorySize,
                         GEMM_SMEM);
    cudaFuncSetAttribute(gemm_tf32<false>, cudaFuncAttributeMaxDynamicSharedMemorySize,
                         GEMM_SMEM);

    // weight permute + tf32 round pre-pass
    int totIn  = NLAYER * PRJ * DM;
    int totOut = NLAYER * DM * DI;
    k_permw<<<(totIn  + 255) / 256, 256>>>(inproj_w, pwin,  totIn,  DM - 1);
    k_permw<<<(totOut + 255) / 256, 256>>>(outp_w,   pwout, totOut, DI - 1);

    k_in_ln<<<BLT, 256>>>(x, in_w, in_b, lnin_w, lnin_b);
    for (int i = 0; i < NLAYER; i++) {
        gemm_tf32<true><<<dim3((PRJ + 127) / 128, BLT / 128), 256, GEMM_SMEM>>>(
            ph, pwin + (size_t)i * PRJ * DM, pzx, BLT, PRJ, DM);
        k_conv<<<(BLT * CCH) / 256, 256>>>(conv_w + i * DCV * CCH, conv_b + i * CCH);
        k_dt<<<(BLT * NHH) / 256, 256>>>(dt_bias + i * NHH, A_log + i * NHH);
        k_scan<<<BB * NHH, 256>>>(Dp + i * NHH);
        k_rms<<<BLT, 256>>>(norm_w + i * DI);
        gemm_tf32<false><<<dim3(DM / 128, BLT / 128), 256, GEMM_SMEM>>>(
            py, pwout + (size_t)i * DM * DI, pm, BLT, DM, DI);
        k_addln<<<BLT, 256>>>(ln_w + i * DM, ln_b + i * DM);
    }
    k_pool<<<dim3(BB, 8), 256>>>(lengths);
    k_head<<<BB, NCLS * 32>>>(head_w, head_b, lengths, out);
}